// round 6
// baseline (speedup 1.0000x reference)
#include <cuda_runtime.h>
#include <cstdint>

#define T_DATA 50000
#define E_NO   1000
#define I_NO   200
#define SUB_NO 20
#define H_NO   16
#define T_NO   200
#define COS_NO 20

// ---------------- persistent scratch (device globals; no allocation) --------
__device__ float g_Sg[2 * SUB_NO][T_DATA];                 // channel-major grouped signals (8 MB)
__device__ float g_partial[SUB_NO][T_DATA];                // per-subunit root partials (4 MB)

__device__ __forceinline__ float lrelu(float x) {
    return x >= 0.0f ? x : 0.01f * x;
}

// ---------------- packed f32x2 helpers (Blackwell) -------------------------
__device__ __forceinline__ unsigned long long f32x2_fma(
    unsigned long long a, unsigned long long b, unsigned long long c)
{
    unsigned long long d;
    asm("fma.rn.f32x2 %0, %1, %2, %3;" : "=l"(d) : "l"(a), "l"(b), "l"(c));
    return d;
}
__device__ __forceinline__ unsigned long long f32x2_pack(float lo, float hi)
{
    unsigned long long r;
    asm("mov.b64 %0, {%1, %2};" : "=l"(r) : "f"(lo), "f"(hi));
    return r;
}
__device__ __forceinline__ void f32x2_unpack(unsigned long long v, float& lo, float& hi)
{
    asm("mov.b64 {%0, %1}, %2;" : "=f"(lo), "=f"(hi) : "l"(v));
}

// ---------------------------------------------------------------------------
// Kernel 1: synthesize the flipped conv_kern output (d_out[T_DATA:]).
// (The conv itself no longer needs the synthesized kernels.)
// ---------------------------------------------------------------------------
__global__ void prep_kern(const float* __restrict__ W_conv,
                          float* __restrict__ out_kern, int write_out)
{
    __shared__ float basis[COS_NO][T_NO];
    const int s = blockIdx.x;
    const float PI = 3.14159265358979323846f;

    for (int idx = threadIdx.x; idx < COS_NO * T_NO; idx += blockDim.x) {
        int b = idx / T_NO, t = idx % T_NO;
        float phi = 1.5707963267948966f * (float)b;
        float raw = 5.0f * logf((float)t + 1.0f);
        float v = 0.5f * cosf(raw - phi) + 0.5f;
        basis[b][t] = (raw >= phi - PI && raw <= phi + PI) ? v : 0.0f;
    }
    __syncthreads();
    if (!write_out) return;

    for (int idx = threadIdx.x; idx < H_NO * 2 * T_NO; idx += blockDim.x) {
        int h = idx / (2 * T_NO);
        int c = (idx / T_NO) & 1;
        int k = idx % T_NO;
        int o = s * H_NO + h;
        const float* w = W_conv + (o * 2 + c) * COS_NO;
        float acc = 0.0f;
#pragma unroll
        for (int b = 0; b < COS_NO; b++) acc = fmaf(w[b], basis[b][k], acc);
        out_kern[(o * 2 + c) * T_NO + (T_NO - 1 - k)] = acc;
    }
}

// ---------------------------------------------------------------------------
// Kernel 2: synapse grouping GEMM (memory-bound; unchanged).
// ---------------------------------------------------------------------------
#define GM_ROWS 128
#define GM_KC   40
#define GM_PAD  44

__global__ __launch_bounds__(256) void group_gemm(
    const float* __restrict__ S_e, const float* __restrict__ S_i,
    const float* __restrict__ Ce,  const float* __restrict__ Ci)
{
    __shared__ float sS[GM_ROWS][GM_PAD];
    __shared__ float sC[SUB_NO][GM_PAD];

    const int t0 = blockIdx.x * GM_ROWS;
    const int tid = threadIdx.x;
    const int w = tid >> 5, lane = tid & 31;
    const int cg = w >> 1;
    const int rh = w & 1;
    const int r0 = rh * 64 + lane;

    for (int ph = 0; ph < 2; ph++) {
        const float* S = ph ? S_i : S_e;
        const float* C = ph ? Ci : Ce;
        const int K = ph ? I_NO : E_NO;

        unsigned long long acc0[5], acc1[5];
#pragma unroll
        for (int j = 0; j < 5; j++) { acc0[j] = 0ULL; acc1[j] = 0ULL; }

        for (int kc = 0; kc < K; kc += GM_KC) {
            {
                int r = tid >> 1, half = tid & 1;
                int row = t0 + r;
#pragma unroll
                for (int j = 0; j < 5; j++) {
                    int col = kc + half * 20 + j * 4;
                    float4 v = make_float4(0.f, 0.f, 0.f, 0.f);
                    if (row < T_DATA)
                        v = *(const float4*)&S[(size_t)row * K + col];
                    *(float4*)&sS[r][half * 20 + j * 4] = v;
                }
            }
            if (tid < 200) {
                int col = tid / 10, seg = tid % 10;
                *(float4*)&sC[col][seg * 4] =
                    *(const float4*)&C[col * K + kc + seg * 4];
            }
            __syncthreads();

#pragma unroll
            for (int k4 = 0; k4 < GM_KC; k4 += 4) {
                float4 a0 = *(float4*)&sS[r0][k4];
                float4 a1 = *(float4*)&sS[r0 + 32][k4];
                unsigned long long a0lo = f32x2_pack(a0.x, a0.y);
                unsigned long long a0hi = f32x2_pack(a0.z, a0.w);
                unsigned long long a1lo = f32x2_pack(a1.x, a1.y);
                unsigned long long a1hi = f32x2_pack(a1.z, a1.w);
#pragma unroll
                for (int j = 0; j < 5; j++) {
                    float4 b = *(float4*)&sC[cg * 5 + j][k4];
                    unsigned long long blo = f32x2_pack(b.x, b.y);
                    unsigned long long bhi = f32x2_pack(b.z, b.w);
                    acc0[j] = f32x2_fma(a0lo, blo, acc0[j]);
                    acc0[j] = f32x2_fma(a0hi, bhi, acc0[j]);
                    acc1[j] = f32x2_fma(a1lo, blo, acc1[j]);
                    acc1[j] = f32x2_fma(a1hi, bhi, acc1[j]);
                }
            }
            __syncthreads();
        }
#pragma unroll
        for (int j = 0; j < 5; j++) {
            int ch = 2 * (cg * 5 + j) + ph;
            float lo, hi;
            if (t0 + r0 < T_DATA) {
                f32x2_unpack(acc0[j], lo, hi);
                g_Sg[ch][t0 + r0] = lo + hi;
            }
            if (t0 + r0 + 32 < T_DATA) {
                f32x2_unpack(acc1[j], lo, hi);
                g_Sg[ch][t0 + r0 + 32] = lo + hi;
            }
        }
    }
}

// ---------------------------------------------------------------------------
// Kernel 3: basis-factored causal conv + mix + 2-layer MLP + root dot.
//   Step A: u[b,t] = sum_k basis[b,k] * win(t-k)   (<=5 active b per k)
//   Step B: x[h,t] = lrelu( sum_b mixW[h,b] . u[b,t] )   (e/i packed in f32x2)
// k is segmented into 16 compile-time ranges where the active-b window
// [j, j+4] is constant, so u2[] uses only static register indices.
// ---------------------------------------------------------------------------
#define CT       512
#define CTHREADS 128

__global__ __launch_bounds__(CTHREADS) void conv_mlp(
    const float* __restrict__ W_conv,
    const float* __restrict__ ff_w,  const float* __restrict__ ff_b,
    const float* __restrict__ ff2_w, const float* __restrict__ ff2_b,
    const float* __restrict__ root_w)
{
    __shared__ unsigned long long basis2k[T_NO][COS_NO];   // {v,v} packed, 32.0 KB
    __shared__ unsigned long long win2[CT + T_NO - 1];     // {e,i} packed, 5.7 KB
    __shared__ unsigned long long mixW2[H_NO][COS_NO];     // {We,Wi} packed, 2.5 KB
    __shared__ float W1[H_NO][H_NO], W2[H_NO][H_NO];
    __shared__ float B1[H_NO], B2[H_NO], RW[H_NO];

    const int s  = blockIdx.y;
    const int t0 = blockIdx.x * CT;
    const int tid = threadIdx.x;
    const float PI = 3.14159265358979323846f;

    // basis table (fast-math is safe: mask boundary is a zero of the basis)
    for (int idx = tid; idx < T_NO * COS_NO; idx += CTHREADS) {
        int k = idx / COS_NO, b = idx % COS_NO;
        float raw = 5.0f * __logf((float)k + 1.0f);
        float d = raw - 1.5707963267948966f * (float)b;
        float v = 0.5f * __cosf(d) + 0.5f;
        v = (d >= -PI && d <= PI) ? v : 0.0f;
        basis2k[k][b] = f32x2_pack(v, v);
    }
    // signal window, e/i packed
    {
        const float* se = g_Sg[2 * s];
        const float* si = g_Sg[2 * s + 1];
        for (int j = tid; j < CT + T_NO - 1; j += CTHREADS) {
            int t = t0 + j - (T_NO - 1);
            float e = 0.0f, iv = 0.0f;
            if (t >= 0 && t < T_DATA) { e = se[t]; iv = si[t]; }
            win2[j] = f32x2_pack(e, iv);
        }
    }
    // mix weights: W_conv used directly (no kernel synthesis needed)
    for (int idx = tid; idx < H_NO * COS_NO; idx += CTHREADS) {
        int h = idx / COS_NO, b = idx % COS_NO;
        int o = s * H_NO + h;
        mixW2[h][b] = f32x2_pack(W_conv[(o * 2 + 0) * COS_NO + b],
                                 W_conv[(o * 2 + 1) * COS_NO + b]);
    }
    // MLP weights
    for (int i = tid; i < H_NO * H_NO; i += CTHREADS) {
        W1[i >> 4][i & 15] = ff_w[s * H_NO * H_NO + i];
        W2[i >> 4][i & 15] = ff2_w[s * H_NO * H_NO + i];
    }
    if (tid < H_NO) {
        B1[tid] = ff_b[s * H_NO + tid];
        B2[tid] = ff2_b[s * H_NO + tid];
        RW[tid] = root_w[s * H_NO + tid];
    }
    __syncthreads();

    // k-segments: window start j is constant on [KSEG[j], KSEG[j+1])
    // (first k with k+1 > e^{(j+1)*pi/10})
    constexpr int KSEG[17] = {0, 1, 2, 3, 4, 6, 9, 12, 16, 23,
                              31, 43, 59, 81, 111, 152, 200};

#pragma unroll 1
    for (int q = 0; q < 4; q++) {
        unsigned long long u2[COS_NO];
#pragma unroll
        for (int b = 0; b < COS_NO; b++) u2[b] = 0ULL;

        const unsigned long long* wq = &win2[tid + q * CTHREADS + (T_NO - 1)];

#pragma unroll
        for (int j = 0; j < 16; j++) {
#pragma unroll 4
            for (int k = KSEG[j]; k < KSEG[j + 1]; k++) {
                unsigned long long wv = wq[-k];
                const unsigned long long* br = &basis2k[k][j];
                u2[j + 0] = f32x2_fma(wv, br[0], u2[j + 0]);
                u2[j + 1] = f32x2_fma(wv, br[1], u2[j + 1]);
                u2[j + 2] = f32x2_fma(wv, br[2], u2[j + 2]);
                u2[j + 3] = f32x2_fma(wv, br[3], u2[j + 3]);
                u2[j + 4] = f32x2_fma(wv, br[4], u2[j + 4]);
            }
        }

        // Step B: mix to 16 hidden channels, then leaky ReLU
        float x[H_NO];
#pragma unroll
        for (int h = 0; h < H_NO; h++) {
            unsigned long long a2 = 0ULL;
#pragma unroll
            for (int b = 0; b < COS_NO; b++)
                a2 = f32x2_fma(u2[b], mixW2[h][b], a2);
            float lo, hi;
            f32x2_unpack(a2, lo, hi);
            x[h] = lrelu(lo + hi);
        }

        // 2-layer MLP + root dot (packed over i)
        unsigned long long xp[8];
#pragma unroll
        for (int p = 0; p < 8; p++) xp[p] = f32x2_pack(x[2 * p], x[2 * p + 1]);

        float h1[H_NO];
#pragma unroll
        for (int o = 0; o < H_NO; o++) {
            const ulonglong2* wrow = (const ulonglong2*)&W1[o][0];
            ulonglong2 w0 = wrow[0], w1 = wrow[1], w2 = wrow[2], w3 = wrow[3];
            unsigned long long a2 = f32x2_fma(xp[0], w0.x, 0ULL);
            a2 = f32x2_fma(xp[1], w0.y, a2);
            a2 = f32x2_fma(xp[2], w1.x, a2);
            a2 = f32x2_fma(xp[3], w1.y, a2);
            a2 = f32x2_fma(xp[4], w2.x, a2);
            a2 = f32x2_fma(xp[5], w2.y, a2);
            a2 = f32x2_fma(xp[6], w3.x, a2);
            a2 = f32x2_fma(xp[7], w3.y, a2);
            float lo, hi;
            f32x2_unpack(a2, lo, hi);
            h1[o] = lrelu(B1[o] + lo + hi);
        }
        unsigned long long hp[8];
#pragma unroll
        for (int p = 0; p < 8; p++) hp[p] = f32x2_pack(h1[2 * p], h1[2 * p + 1]);

        float pacc = 0.0f;
#pragma unroll
        for (int o = 0; o < H_NO; o++) {
            const ulonglong2* wrow = (const ulonglong2*)&W2[o][0];
            ulonglong2 w0 = wrow[0], w1 = wrow[1], w2 = wrow[2], w3 = wrow[3];
            unsigned long long a2 = f32x2_fma(hp[0], w0.x, 0ULL);
            a2 = f32x2_fma(hp[1], w0.y, a2);
            a2 = f32x2_fma(hp[2], w1.x, a2);
            a2 = f32x2_fma(hp[3], w1.y, a2);
            a2 = f32x2_fma(hp[4], w2.x, a2);
            a2 = f32x2_fma(hp[5], w2.y, a2);
            a2 = f32x2_fma(hp[6], w3.x, a2);
            a2 = f32x2_fma(hp[7], w3.y, a2);
            float lo, hi;
            f32x2_unpack(a2, lo, hi);
            pacc = fmaf(lrelu(B2[o] + lo + hi), RW[o], pacc);
        }
        int t = t0 + tid + q * CTHREADS;
        if (t < T_DATA) g_partial[s][t] = pacc;
    }
}

// ---------------------------------------------------------------------------
// Kernel 4: V[t] = sum_s partial[s][t] + root_b + V_o
// ---------------------------------------------------------------------------
__global__ void finalize(const float* __restrict__ root_b,
                         const float* __restrict__ V_o,
                         float* __restrict__ out)
{
    int t = blockIdx.x * 256 + threadIdx.x;
    if (t >= T_DATA) return;
    float sum = root_b[0] + V_o[0];
#pragma unroll
    for (int s = 0; s < SUB_NO; s++) sum += g_partial[s][t];
    out[t] = sum;
}

// ---------------------------------------------------------------------------
extern "C" void kernel_launch(void* const* d_in, const int* in_sizes, int n_in,
                              void* d_out, int out_size)
{
    const float* S_e    = (const float*)d_in[0];
    const float* S_i    = (const float*)d_in[1];
    const float* C_e    = (const float*)d_in[2];
    const float* C_i    = (const float*)d_in[3];
    const float* W_conv = (const float*)d_in[4];
    const float* ff_w   = (const float*)d_in[5];
    const float* ff_b   = (const float*)d_in[6];
    const float* ff2_w  = (const float*)d_in[7];
    const float* ff2_b  = (const float*)d_in[8];
    const float* root_w = (const float*)d_in[9];
    const float* root_b = (const float*)d_in[10];
    const float* V_o    = (const float*)d_in[11];
    (void)in_sizes; (void)n_in;

    float* out = (float*)d_out;
    const int kern_elems = SUB_NO * H_NO * 2 * T_NO;
    int write_kern = (out_size >= T_DATA + kern_elems) ? 1 : 0;

    prep_kern<<<SUB_NO, 256>>>(W_conv, out + T_DATA, write_kern);

    group_gemm<<<(T_DATA + GM_ROWS - 1) / GM_ROWS, 256>>>(S_e, S_i, C_e, C_i);

    dim3 cgrid((T_DATA + CT - 1) / CT, SUB_NO);
    conv_mlp<<<cgrid, CTHREADS>>>(W_conv, ff_w, ff_b, ff2_w, ff2_b, root_w);

    finalize<<<(T_DATA + 255) / 256, 256>>>(root_b, V_o, out);
}

// round 7
// speedup vs baseline: 1.1711x; 1.1711x over previous
#include <cuda_runtime.h>
#include <cstdint>

#define T_DATA 50000
#define E_NO   1000
#define I_NO   200
#define SUB_NO 20
#define H_NO   16
#define T_NO   200
#define COS_NO 20

// ---------------- persistent scratch (device globals; no allocation) --------
__device__ float g_Sg[2 * SUB_NO][T_DATA];                 // channel-major grouped signals (8 MB)
__device__ float g_partial[SUB_NO][T_DATA];                // per-subunit root partials (4 MB)

__device__ __forceinline__ float lrelu(float x) {
    return x >= 0.0f ? x : 0.01f * x;
}

// ---------------- packed f32x2 helpers (Blackwell) -------------------------
__device__ __forceinline__ unsigned long long f32x2_fma(
    unsigned long long a, unsigned long long b, unsigned long long c)
{
    unsigned long long d;
    asm("fma.rn.f32x2 %0, %1, %2, %3;" : "=l"(d) : "l"(a), "l"(b), "l"(c));
    return d;
}
__device__ __forceinline__ unsigned long long f32x2_pack(float lo, float hi)
{
    unsigned long long r;
    asm("mov.b64 %0, {%1, %2};" : "=l"(r) : "f"(lo), "f"(hi));
    return r;
}
__device__ __forceinline__ void f32x2_unpack(unsigned long long v, float& lo, float& hi)
{
    asm("mov.b64 {%0, %1}, %2;" : "=f"(lo), "=f"(hi) : "l"(v));
}

// ---------------------------------------------------------------------------
// Kernel 1: synthesize the flipped conv_kern output (d_out[T_DATA:]).
// ---------------------------------------------------------------------------
__global__ void prep_kern(const float* __restrict__ W_conv,
                          float* __restrict__ out_kern, int write_out)
{
    __shared__ float basis[COS_NO][T_NO];
    const int s = blockIdx.x;
    const float PI = 3.14159265358979323846f;

    for (int idx = threadIdx.x; idx < COS_NO * T_NO; idx += blockDim.x) {
        int b = idx / T_NO, t = idx % T_NO;
        float phi = 1.5707963267948966f * (float)b;
        float raw = 5.0f * logf((float)t + 1.0f);
        float v = 0.5f * cosf(raw - phi) + 0.5f;
        basis[b][t] = (raw >= phi - PI && raw <= phi + PI) ? v : 0.0f;
    }
    __syncthreads();
    if (!write_out) return;

    for (int idx = threadIdx.x; idx < H_NO * 2 * T_NO; idx += blockDim.x) {
        int h = idx / (2 * T_NO);
        int c = (idx / T_NO) & 1;
        int k = idx % T_NO;
        int o = s * H_NO + h;
        const float* w = W_conv + (o * 2 + c) * COS_NO;
        float acc = 0.0f;
#pragma unroll
        for (int b = 0; b < COS_NO; b++) acc = fmaf(w[b], basis[b][k], acc);
        out_kern[(o * 2 + c) * T_NO + (T_NO - 1 - k)] = acc;
    }
}

// ---------------------------------------------------------------------------
// Kernel 2: synapse grouping GEMM (memory-bound; unchanged).
// ---------------------------------------------------------------------------
#define GM_ROWS 128
#define GM_KC   40
#define GM_PAD  44

__global__ __launch_bounds__(256) void group_gemm(
    const float* __restrict__ S_e, const float* __restrict__ S_i,
    const float* __restrict__ Ce,  const float* __restrict__ Ci)
{
    __shared__ float sS[GM_ROWS][GM_PAD];
    __shared__ float sC[SUB_NO][GM_PAD];

    const int t0 = blockIdx.x * GM_ROWS;
    const int tid = threadIdx.x;
    const int w = tid >> 5, lane = tid & 31;
    const int cg = w >> 1;
    const int rh = w & 1;
    const int r0 = rh * 64 + lane;

    for (int ph = 0; ph < 2; ph++) {
        const float* S = ph ? S_i : S_e;
        const float* C = ph ? Ci : Ce;
        const int K = ph ? I_NO : E_NO;

        unsigned long long acc0[5], acc1[5];
#pragma unroll
        for (int j = 0; j < 5; j++) { acc0[j] = 0ULL; acc1[j] = 0ULL; }

        for (int kc = 0; kc < K; kc += GM_KC) {
            {
                int r = tid >> 1, half = tid & 1;
                int row = t0 + r;
#pragma unroll
                for (int j = 0; j < 5; j++) {
                    int col = kc + half * 20 + j * 4;
                    float4 v = make_float4(0.f, 0.f, 0.f, 0.f);
                    if (row < T_DATA)
                        v = *(const float4*)&S[(size_t)row * K + col];
                    *(float4*)&sS[r][half * 20 + j * 4] = v;
                }
            }
            if (tid < 200) {
                int col = tid / 10, seg = tid % 10;
                *(float4*)&sC[col][seg * 4] =
                    *(const float4*)&C[col * K + kc + seg * 4];
            }
            __syncthreads();

#pragma unroll
            for (int k4 = 0; k4 < GM_KC; k4 += 4) {
                float4 a0 = *(float4*)&sS[r0][k4];
                float4 a1 = *(float4*)&sS[r0 + 32][k4];
                unsigned long long a0lo = f32x2_pack(a0.x, a0.y);
                unsigned long long a0hi = f32x2_pack(a0.z, a0.w);
                unsigned long long a1lo = f32x2_pack(a1.x, a1.y);
                unsigned long long a1hi = f32x2_pack(a1.z, a1.w);
#pragma unroll
                for (int j = 0; j < 5; j++) {
                    float4 b = *(float4*)&sC[cg * 5 + j][k4];
                    unsigned long long blo = f32x2_pack(b.x, b.y);
                    unsigned long long bhi = f32x2_pack(b.z, b.w);
                    acc0[j] = f32x2_fma(a0lo, blo, acc0[j]);
                    acc0[j] = f32x2_fma(a0hi, bhi, acc0[j]);
                    acc1[j] = f32x2_fma(a1lo, blo, acc1[j]);
                    acc1[j] = f32x2_fma(a1hi, bhi, acc1[j]);
                }
            }
            __syncthreads();
        }
#pragma unroll
        for (int j = 0; j < 5; j++) {
            int ch = 2 * (cg * 5 + j) + ph;
            float lo, hi;
            if (t0 + r0 < T_DATA) {
                f32x2_unpack(acc0[j], lo, hi);
                g_Sg[ch][t0 + r0] = lo + hi;
            }
            if (t0 + r0 + 32 < T_DATA) {
                f32x2_unpack(acc1[j], lo, hi);
                g_Sg[ch][t0 + r0 + 32] = lo + hi;
            }
        }
    }
}

// ---------------------------------------------------------------------------
// Kernel 3: basis-factored causal conv + mix + 2-layer MLP + root dot.
// Step A batches TWO t's per tap (basis loads amortized); k-loops are rolled
// (small I$ body), segments j unrolled so u[] indices stay static.
// ---------------------------------------------------------------------------
#define CT       512
#define CTHREADS 128

__global__ __launch_bounds__(CTHREADS) void conv_mlp(
    const float* __restrict__ W_conv,
    const float* __restrict__ ff_w,  const float* __restrict__ ff_b,
    const float* __restrict__ ff2_w, const float* __restrict__ ff2_b,
    const float* __restrict__ root_w)
{
    __shared__ unsigned long long basis2k[T_NO][COS_NO];   // {v,v} packed, 32.0 KB
    __shared__ unsigned long long win2[CT + T_NO - 1];     // {e,i} packed, 5.7 KB
    __shared__ unsigned long long mixW2[H_NO][COS_NO];     // {We,Wi} packed, 2.5 KB
    __shared__ float W1[H_NO][H_NO], W2[H_NO][H_NO];
    __shared__ float B1[H_NO], B2[H_NO], RW[H_NO];

    const int s  = blockIdx.y;
    const int t0 = blockIdx.x * CT;
    const int tid = threadIdx.x;
    const float PI = 3.14159265358979323846f;

    // basis table (fast-math safe: mask boundary is a zero of the basis)
    for (int idx = tid; idx < T_NO * COS_NO; idx += CTHREADS) {
        int k = idx / COS_NO, b = idx % COS_NO;
        float raw = 5.0f * __logf((float)k + 1.0f);
        float d = raw - 1.5707963267948966f * (float)b;
        float v = 0.5f * __cosf(d) + 0.5f;
        v = (d >= -PI && d <= PI) ? v : 0.0f;
        basis2k[k][b] = f32x2_pack(v, v);
    }
    // signal window, e/i packed
    {
        const float* se = g_Sg[2 * s];
        const float* si = g_Sg[2 * s + 1];
        for (int j = tid; j < CT + T_NO - 1; j += CTHREADS) {
            int t = t0 + j - (T_NO - 1);
            float e = 0.0f, iv = 0.0f;
            if (t >= 0 && t < T_DATA) { e = se[t]; iv = si[t]; }
            win2[j] = f32x2_pack(e, iv);
        }
    }
    // mix weights (W_conv used directly)
    for (int idx = tid; idx < H_NO * COS_NO; idx += CTHREADS) {
        int h = idx / COS_NO, b = idx % COS_NO;
        int o = s * H_NO + h;
        mixW2[h][b] = f32x2_pack(W_conv[(o * 2 + 0) * COS_NO + b],
                                 W_conv[(o * 2 + 1) * COS_NO + b]);
    }
    // MLP weights
    for (int i = tid; i < H_NO * H_NO; i += CTHREADS) {
        W1[i >> 4][i & 15] = ff_w[s * H_NO * H_NO + i];
        W2[i >> 4][i & 15] = ff2_w[s * H_NO * H_NO + i];
    }
    if (tid < H_NO) {
        B1[tid] = ff_b[s * H_NO + tid];
        B2[tid] = ff2_b[s * H_NO + tid];
        RW[tid] = root_w[s * H_NO + tid];
    }
    __syncthreads();

    // k-segments: active bases are [j, j+4] for k in [KSEG[j], KSEG[j+1])
    constexpr int KSEG[17] = {0, 1, 2, 3, 4, 6, 9, 12, 16, 23,
                              31, 43, 59, 81, 111, 152, 200};

#pragma unroll 1
    for (int qq = 0; qq < 2; qq++) {
        // pair of time points: ta = t0+tid+qq*256, tb = ta+128
        unsigned long long ua[COS_NO], ub[COS_NO];
#pragma unroll
        for (int b = 0; b < COS_NO; b++) { ua[b] = 0ULL; ub[b] = 0ULL; }

        const unsigned long long* wa0 = &win2[tid + qq * 256 + (T_NO - 1)];
        const unsigned long long* wb0 = wa0 + CTHREADS;

#pragma unroll
        for (int j = 0; j < 16; j++) {
            const unsigned long long* br = &basis2k[KSEG[j]][j];
            const unsigned long long* wa = wa0 - KSEG[j];
            const unsigned long long* wb = wb0 - KSEG[j];
#pragma unroll 1
            for (int k = KSEG[j]; k < KSEG[j + 1]; k++) {
                unsigned long long va = *wa;
                unsigned long long vb = *wb;
                unsigned long long b0 = br[0], b1 = br[1], b2 = br[2],
                                   b3 = br[3], b4 = br[4];
                ua[j + 0] = f32x2_fma(va, b0, ua[j + 0]);
                ub[j + 0] = f32x2_fma(vb, b0, ub[j + 0]);
                ua[j + 1] = f32x2_fma(va, b1, ua[j + 1]);
                ub[j + 1] = f32x2_fma(vb, b1, ub[j + 1]);
                ua[j + 2] = f32x2_fma(va, b2, ua[j + 2]);
                ub[j + 2] = f32x2_fma(vb, b2, ub[j + 2]);
                ua[j + 3] = f32x2_fma(va, b3, ua[j + 3]);
                ub[j + 3] = f32x2_fma(vb, b3, ub[j + 3]);
                ua[j + 4] = f32x2_fma(va, b4, ua[j + 4]);
                ub[j + 4] = f32x2_fma(vb, b4, ub[j + 4]);
                br += COS_NO;
                wa -= 1;
                wb -= 1;
            }
        }

        // Step B: mix to 16 hidden channels for both t's (weights loaded once)
        float xa[H_NO], xb[H_NO];
#pragma unroll
        for (int h = 0; h < H_NO; h++) {
            unsigned long long a2 = 0ULL, b2 = 0ULL;
#pragma unroll
            for (int b = 0; b < COS_NO; b++) {
                unsigned long long m = mixW2[h][b];
                a2 = f32x2_fma(ua[b], m, a2);
                b2 = f32x2_fma(ub[b], m, b2);
            }
            float lo, hi;
            f32x2_unpack(a2, lo, hi);
            xa[h] = lrelu(lo + hi);
            f32x2_unpack(b2, lo, hi);
            xb[h] = lrelu(lo + hi);
        }

        unsigned long long xpa[8], xpb[8];
#pragma unroll
        for (int p = 0; p < 8; p++) {
            xpa[p] = f32x2_pack(xa[2 * p], xa[2 * p + 1]);
            xpb[p] = f32x2_pack(xb[2 * p], xb[2 * p + 1]);
        }

        float h1a[H_NO], h1b[H_NO];
#pragma unroll
        for (int o = 0; o < H_NO; o++) {
            const ulonglong2* wrow = (const ulonglong2*)&W1[o][0];
            ulonglong2 w0 = wrow[0], w1 = wrow[1], w2 = wrow[2], w3 = wrow[3];
            unsigned long long a2 = f32x2_fma(xpa[0], w0.x, 0ULL);
            unsigned long long b2 = f32x2_fma(xpb[0], w0.x, 0ULL);
            a2 = f32x2_fma(xpa[1], w0.y, a2);  b2 = f32x2_fma(xpb[1], w0.y, b2);
            a2 = f32x2_fma(xpa[2], w1.x, a2);  b2 = f32x2_fma(xpb[2], w1.x, b2);
            a2 = f32x2_fma(xpa[3], w1.y, a2);  b2 = f32x2_fma(xpb[3], w1.y, b2);
            a2 = f32x2_fma(xpa[4], w2.x, a2);  b2 = f32x2_fma(xpb[4], w2.x, b2);
            a2 = f32x2_fma(xpa[5], w2.y, a2);  b2 = f32x2_fma(xpb[5], w2.y, b2);
            a2 = f32x2_fma(xpa[6], w3.x, a2);  b2 = f32x2_fma(xpb[6], w3.x, b2);
            a2 = f32x2_fma(xpa[7], w3.y, a2);  b2 = f32x2_fma(xpb[7], w3.y, b2);
            float lo, hi;
            f32x2_unpack(a2, lo, hi);
            h1a[o] = lrelu(B1[o] + lo + hi);
            f32x2_unpack(b2, lo, hi);
            h1b[o] = lrelu(B1[o] + lo + hi);
        }

        unsigned long long hpa[8], hpb[8];
#pragma unroll
        for (int p = 0; p < 8; p++) {
            hpa[p] = f32x2_pack(h1a[2 * p], h1a[2 * p + 1]);
            hpb[p] = f32x2_pack(h1b[2 * p], h1b[2 * p + 1]);
        }

        float pacc_a = 0.0f, pacc_b = 0.0f;
#pragma unroll
        for (int o = 0; o < H_NO; o++) {
            const ulonglong2* wrow = (const ulonglong2*)&W2[o][0];
            ulonglong2 w0 = wrow[0], w1 = wrow[1], w2 = wrow[2], w3 = wrow[3];
            unsigned long long a2 = f32x2_fma(hpa[0], w0.x, 0ULL);
            unsigned long long b2 = f32x2_fma(hpb[0], w0.x, 0ULL);
            a2 = f32x2_fma(hpa[1], w0.y, a2);  b2 = f32x2_fma(hpb[1], w0.y, b2);
            a2 = f32x2_fma(hpa[2], w1.x, a2);  b2 = f32x2_fma(hpb[2], w1.x, b2);
            a2 = f32x2_fma(hpa[3], w1.y, a2);  b2 = f32x2_fma(hpb[3], w1.y, b2);
            a2 = f32x2_fma(hpa[4], w2.x, a2);  b2 = f32x2_fma(hpb[4], w2.x, b2);
            a2 = f32x2_fma(hpa[5], w2.y, a2);  b2 = f32x2_fma(hpb[5], w2.y, b2);
            a2 = f32x2_fma(hpa[6], w3.x, a2);  b2 = f32x2_fma(hpb[6], w3.x, b2);
            a2 = f32x2_fma(hpa[7], w3.y, a2);  b2 = f32x2_fma(hpb[7], w3.y, b2);
            float lo, hi;
            f32x2_unpack(a2, lo, hi);
            pacc_a = fmaf(lrelu(B2[o] + lo + hi), RW[o], pacc_a);
            f32x2_unpack(b2, lo, hi);
            pacc_b = fmaf(lrelu(B2[o] + lo + hi), RW[o], pacc_b);
        }

        int ta = t0 + tid + qq * 256;
        int tb = ta + CTHREADS;
        if (ta < T_DATA) g_partial[s][ta] = pacc_a;
        if (tb < T_DATA) g_partial[s][tb] = pacc_b;
    }
}

// ---------------------------------------------------------------------------
// Kernel 4: V[t] = sum_s partial[s][t] + root_b + V_o
// ---------------------------------------------------------------------------
__global__ void finalize(const float* __restrict__ root_b,
                         const float* __restrict__ V_o,
                         float* __restrict__ out)
{
    int t = blockIdx.x * 256 + threadIdx.x;
    if (t >= T_DATA) return;
    float sum = root_b[0] + V_o[0];
#pragma unroll
    for (int s = 0; s < SUB_NO; s++) sum += g_partial[s][t];
    out[t] = sum;
}

// ---------------------------------------------------------------------------
extern "C" void kernel_launch(void* const* d_in, const int* in_sizes, int n_in,
                              void* d_out, int out_size)
{
    const float* S_e    = (const float*)d_in[0];
    const float* S_i    = (const float*)d_in[1];
    const float* C_e    = (const float*)d_in[2];
    const float* C_i    = (const float*)d_in[3];
    const float* W_conv = (const float*)d_in[4];
    const float* ff_w   = (const float*)d_in[5];
    const float* ff_b   = (const float*)d_in[6];
    const float* ff2_w  = (const float*)d_in[7];
    const float* ff2_b  = (const float*)d_in[8];
    const float* root_w = (const float*)d_in[9];
    const float* root_b = (const float*)d_in[10];
    const float* V_o    = (const float*)d_in[11];
    (void)in_sizes; (void)n_in;

    float* out = (float*)d_out;
    const int kern_elems = SUB_NO * H_NO * 2 * T_NO;
    int write_kern = (out_size >= T_DATA + kern_elems) ? 1 : 0;

    prep_kern<<<SUB_NO, 256>>>(W_conv, out + T_DATA, write_kern);

    group_gemm<<<(T_DATA + GM_ROWS - 1) / GM_ROWS, 256>>>(S_e, S_i, C_e, C_i);

    dim3 cgrid((T_DATA + CT - 1) / CT, SUB_NO);
    conv_mlp<<<cgrid, CTHREADS>>>(W_conv, ff_w, ff_b, ff2_w, ff2_b, root_w);

    finalize<<<(T_DATA + 255) / 256, 256>>>(root_b, V_o, out);
}

// round 9
// speedup vs baseline: 1.2556x; 1.0721x over previous
#include <cuda_runtime.h>
#include <cstdint>

#define T_DATA 50000
#define E_NO   1000
#define I_NO   200
#define SUB_NO 20
#define H_NO   16
#define T_NO   200
#define COS_NO 20

// ---------------- persistent scratch (device globals; no allocation) --------
__device__ float g_Sg[2 * SUB_NO][T_DATA];                 // channel-major grouped signals (8 MB)
__device__ float g_partial[SUB_NO][T_DATA];                // per-subunit root partials (4 MB)

__device__ __forceinline__ float lrelu(float x) {
    return x >= 0.0f ? x : 0.01f * x;
}

// ---------------- packed f32x2 helpers (Blackwell) -------------------------
__device__ __forceinline__ unsigned long long f32x2_fma(
    unsigned long long a, unsigned long long b, unsigned long long c)
{
    unsigned long long d;
    asm("fma.rn.f32x2 %0, %1, %2, %3;" : "=l"(d) : "l"(a), "l"(b), "l"(c));
    return d;
}
__device__ __forceinline__ unsigned long long f32x2_pack(float lo, float hi)
{
    unsigned long long r;
    asm("mov.b64 %0, {%1, %2};" : "=l"(r) : "f"(lo), "f"(hi));
    return r;
}
__device__ __forceinline__ void f32x2_unpack(unsigned long long v, float& lo, float& hi)
{
    asm("mov.b64 {%0, %1}, %2;" : "=f"(lo), "=f"(hi) : "l"(v));
}

// ---------------------------------------------------------------------------
// Kernel 1: synthesize the flipped conv_kern output (d_out[T_DATA:]).
// ---------------------------------------------------------------------------
__global__ void prep_kern(const float* __restrict__ W_conv,
                          float* __restrict__ out_kern, int write_out)
{
    __shared__ float basis[COS_NO][T_NO];
    const int s = blockIdx.x;
    const float PI = 3.14159265358979323846f;

    for (int idx = threadIdx.x; idx < COS_NO * T_NO; idx += blockDim.x) {
        int b = idx / T_NO, t = idx % T_NO;
        float phi = 1.5707963267948966f * (float)b;
        float raw = 5.0f * logf((float)t + 1.0f);
        float v = 0.5f * cosf(raw - phi) + 0.5f;
        basis[b][t] = (raw >= phi - PI && raw <= phi + PI) ? v : 0.0f;
    }
    __syncthreads();
    if (!write_out) return;

    for (int idx = threadIdx.x; idx < H_NO * 2 * T_NO; idx += blockDim.x) {
        int h = idx / (2 * T_NO);
        int c = (idx / T_NO) & 1;
        int k = idx % T_NO;
        int o = s * H_NO + h;
        const float* w = W_conv + (o * 2 + c) * COS_NO;
        float acc = 0.0f;
#pragma unroll
        for (int b = 0; b < COS_NO; b++) acc = fmaf(w[b], basis[b][k], acc);
        out_kern[(o * 2 + c) * T_NO + (T_NO - 1 - k)] = acc;
    }
}

// ---------------------------------------------------------------------------
// Kernel 2: synapse grouping GEMM (memory-bound; unchanged).
// ---------------------------------------------------------------------------
#define GM_ROWS 128
#define GM_KC   40
#define GM_PAD  44

__global__ __launch_bounds__(256) void group_gemm(
    const float* __restrict__ S_e, const float* __restrict__ S_i,
    const float* __restrict__ Ce,  const float* __restrict__ Ci)
{
    __shared__ float sS[GM_ROWS][GM_PAD];
    __shared__ float sC[SUB_NO][GM_PAD];

    const int t0 = blockIdx.x * GM_ROWS;
    const int tid = threadIdx.x;
    const int w = tid >> 5, lane = tid & 31;
    const int cg = w >> 1;
    const int rh = w & 1;
    const int r0 = rh * 64 + lane;

    for (int ph = 0; ph < 2; ph++) {
        const float* S = ph ? S_i : S_e;
        const float* C = ph ? Ci : Ce;
        const int K = ph ? I_NO : E_NO;

        unsigned long long acc0[5], acc1[5];
#pragma unroll
        for (int j = 0; j < 5; j++) { acc0[j] = 0ULL; acc1[j] = 0ULL; }

        for (int kc = 0; kc < K; kc += GM_KC) {
            {
                int r = tid >> 1, half = tid & 1;
                int row = t0 + r;
#pragma unroll
                for (int j = 0; j < 5; j++) {
                    int col = kc + half * 20 + j * 4;
                    float4 v = make_float4(0.f, 0.f, 0.f, 0.f);
                    if (row < T_DATA)
                        v = *(const float4*)&S[(size_t)row * K + col];
                    *(float4*)&sS[r][half * 20 + j * 4] = v;
                }
            }
            if (tid < 200) {
                int col = tid / 10, seg = tid % 10;
                *(float4*)&sC[col][seg * 4] =
                    *(const float4*)&C[col * K + kc + seg * 4];
            }
            __syncthreads();

#pragma unroll
            for (int k4 = 0; k4 < GM_KC; k4 += 4) {
                float4 a0 = *(float4*)&sS[r0][k4];
                float4 a1 = *(float4*)&sS[r0 + 32][k4];
                unsigned long long a0lo = f32x2_pack(a0.x, a0.y);
                unsigned long long a0hi = f32x2_pack(a0.z, a0.w);
                unsigned long long a1lo = f32x2_pack(a1.x, a1.y);
                unsigned long long a1hi = f32x2_pack(a1.z, a1.w);
#pragma unroll
                for (int j = 0; j < 5; j++) {
                    float4 b = *(float4*)&sC[cg * 5 + j][k4];
                    unsigned long long blo = f32x2_pack(b.x, b.y);
                    unsigned long long bhi = f32x2_pack(b.z, b.w);
                    acc0[j] = f32x2_fma(a0lo, blo, acc0[j]);
                    acc0[j] = f32x2_fma(a0hi, bhi, acc0[j]);
                    acc1[j] = f32x2_fma(a1lo, blo, acc1[j]);
                    acc1[j] = f32x2_fma(a1hi, bhi, acc1[j]);
                }
            }
            __syncthreads();
        }
#pragma unroll
        for (int j = 0; j < 5; j++) {
            int ch = 2 * (cg * 5 + j) + ph;
            float lo, hi;
            if (t0 + r0 < T_DATA) {
                f32x2_unpack(acc0[j], lo, hi);
                g_Sg[ch][t0 + r0] = lo + hi;
            }
            if (t0 + r0 + 32 < T_DATA) {
                f32x2_unpack(acc1[j], lo, hi);
                g_Sg[ch][t0 + r0 + 32] = lo + hi;
            }
        }
    }
}

// ---------------------------------------------------------------------------
// Kernel 3: basis-factored causal conv + mix + 2-layer MLP + root dot.
// Step A: 2 t's per thread per pass; basis in segment-major padded rows
// (48 B -> 3x LDS.128 per tap); inner k-loop unrolled by 2 taps for ILP.
// ---------------------------------------------------------------------------
#define CT       512
#define CTHREADS 128

__global__ __launch_bounds__(CTHREADS) void conv_mlp(
    const float* __restrict__ W_conv,
    const float* __restrict__ ff_w,  const float* __restrict__ ff_b,
    const float* __restrict__ ff2_w, const float* __restrict__ ff2_b,
    const float* __restrict__ root_w)
{
    // bseg[k][0..4] = basis(b = jseg(k)+slot, k) packed {v,v}; [5] = pad.
    __shared__ unsigned long long bseg[T_NO][6];           // 9.6 KB
    __shared__ unsigned long long win2[CT + T_NO - 1];     // {e,i} packed, 5.7 KB
    __shared__ unsigned long long mixW2[H_NO][COS_NO];     // {We,Wi} packed, 2.5 KB
    __shared__ float W1[H_NO][H_NO], W2[H_NO][H_NO];
    __shared__ float B1[H_NO], B2[H_NO], RW[H_NO];

    const int s  = blockIdx.y;
    const int t0 = blockIdx.x * CT;
    const int tid = threadIdx.x;
    const float PI = 3.14159265358979323846f;

    // k-segments: active bases are [j, j+4] for k in [KSEG[j], KSEG[j+1])
    constexpr int KSEG[17] = {0, 1, 2, 3, 4, 6, 9, 12, 16, 23,
                              31, 43, 59, 81, 111, 152, 200};

    // basis fill: same KSEG table decides the window (exact consistency)
    for (int idx = tid; idx < T_NO * 5; idx += CTHREADS) {
        int k = idx / 5, slot = idx % 5;
        int j = 0;
#pragma unroll
        for (int jj = 1; jj < 16; jj++) if (k >= KSEG[jj]) j = jj;
        int b = j + slot;                       // <= 19 always
        float raw = 5.0f * __logf((float)k + 1.0f);
        float d = raw - 1.5707963267948966f * (float)b;
        float v = 0.5f * __cosf(d) + 0.5f;
        v = (d >= -PI && d <= PI) ? v : 0.0f;
        bseg[k][slot] = f32x2_pack(v, v);
    }
    for (int k = tid; k < T_NO; k += CTHREADS) bseg[k][5] = 0ULL;

    // signal window, e/i packed
    {
        const float* se = g_Sg[2 * s];
        const float* si = g_Sg[2 * s + 1];
        for (int j = tid; j < CT + T_NO - 1; j += CTHREADS) {
            int t = t0 + j - (T_NO - 1);
            float e = 0.0f, iv = 0.0f;
            if (t >= 0 && t < T_DATA) { e = se[t]; iv = si[t]; }
            win2[j] = f32x2_pack(e, iv);
        }
    }
    // mix weights (W_conv used directly)
    for (int idx = tid; idx < H_NO * COS_NO; idx += CTHREADS) {
        int h = idx / COS_NO, b = idx % COS_NO;
        int o = s * H_NO + h;
        mixW2[h][b] = f32x2_pack(W_conv[(o * 2 + 0) * COS_NO + b],
                                 W_conv[(o * 2 + 1) * COS_NO + b]);
    }
    // MLP weights
    for (int i = tid; i < H_NO * H_NO; i += CTHREADS) {
        W1[i >> 4][i & 15] = ff_w[s * H_NO * H_NO + i];
        W2[i >> 4][i & 15] = ff2_w[s * H_NO * H_NO + i];
    }
    if (tid < H_NO) {
        B1[tid] = ff_b[s * H_NO + tid];
        B2[tid] = ff2_b[s * H_NO + tid];
        RW[tid] = root_w[s * H_NO + tid];
    }
    __syncthreads();

#pragma unroll 1
    for (int qq = 0; qq < 2; qq++) {
        unsigned long long ua[COS_NO], ub[COS_NO];
#pragma unroll
        for (int b = 0; b < COS_NO; b++) { ua[b] = 0ULL; ub[b] = 0ULL; }

        const unsigned long long* wa0 = &win2[tid + qq * 256 + (T_NO - 1)];
        const unsigned long long* wb0 = wa0 + CTHREADS;

#pragma unroll
        for (int j = 0; j < 16; j++) {
            int k = KSEG[j];
            const int kend = KSEG[j + 1];
            const ulonglong2* bp = (const ulonglong2*)&bseg[k][0];
            const unsigned long long* wa = wa0 - k;
            const unsigned long long* wb = wb0 - k;
#pragma unroll 1
            for (; k + 2 <= kend; k += 2) {
                ulonglong2 p0 = bp[0], p1 = bp[1], p2 = bp[2];
                ulonglong2 q0 = bp[3], q1 = bp[4], q2 = bp[5];
                unsigned long long va0 = wa[0],  vb0 = wb[0];
                unsigned long long va1 = wa[-1], vb1 = wb[-1];
                // tap k
                ua[j + 0] = f32x2_fma(va0, p0.x, ua[j + 0]);
                ub[j + 0] = f32x2_fma(vb0, p0.x, ub[j + 0]);
                ua[j + 1] = f32x2_fma(va0, p0.y, ua[j + 1]);
                ub[j + 1] = f32x2_fma(vb0, p0.y, ub[j + 1]);
                ua[j + 2] = f32x2_fma(va0, p1.x, ua[j + 2]);
                ub[j + 2] = f32x2_fma(vb0, p1.x, ub[j + 2]);
                ua[j + 3] = f32x2_fma(va0, p1.y, ua[j + 3]);
                ub[j + 3] = f32x2_fma(vb0, p1.y, ub[j + 3]);
                ua[j + 4] = f32x2_fma(va0, p2.x, ua[j + 4]);
                ub[j + 4] = f32x2_fma(vb0, p2.x, ub[j + 4]);
                // tap k+1
                ua[j + 0] = f32x2_fma(va1, q0.x, ua[j + 0]);
                ub[j + 0] = f32x2_fma(vb1, q0.x, ub[j + 0]);
                ua[j + 1] = f32x2_fma(va1, q0.y, ua[j + 1]);
                ub[j + 1] = f32x2_fma(vb1, q0.y, ub[j + 1]);
                ua[j + 2] = f32x2_fma(va1, q1.x, ua[j + 2]);
                ub[j + 2] = f32x2_fma(vb1, q1.x, ub[j + 2]);
                ua[j + 3] = f32x2_fma(va1, q1.y, ua[j + 3]);
                ub[j + 3] = f32x2_fma(vb1, q1.y, ub[j + 3]);
                ua[j + 4] = f32x2_fma(va1, q2.x, ua[j + 4]);
                ub[j + 4] = f32x2_fma(vb1, q2.x, ub[j + 4]);
                bp += 6; wa -= 2; wb -= 2;
            }
            if (k < kend) {
                ulonglong2 p0 = bp[0], p1 = bp[1], p2 = bp[2];
                unsigned long long va0 = wa[0], vb0 = wb[0];
                ua[j + 0] = f32x2_fma(va0, p0.x, ua[j + 0]);
                ub[j + 0] = f32x2_fma(vb0, p0.x, ub[j + 0]);
                ua[j + 1] = f32x2_fma(va0, p0.y, ua[j + 1]);
                ub[j + 1] = f32x2_fma(vb0, p0.y, ub[j + 1]);
                ua[j + 2] = f32x2_fma(va0, p1.x, ua[j + 2]);
                ub[j + 2] = f32x2_fma(vb0, p1.x, ub[j + 2]);
                ua[j + 3] = f32x2_fma(va0, p1.y, ua[j + 3]);
                ub[j + 3] = f32x2_fma(vb0, p1.y, ub[j + 3]);
                ua[j + 4] = f32x2_fma(va0, p2.x, ua[j + 4]);
                ub[j + 4] = f32x2_fma(vb0, p2.x, ub[j + 4]);
            }
        }

        // Step B: mix to 16 hidden channels for both t's (weights loaded once)
        float xa[H_NO], xb[H_NO];
#pragma unroll
        for (int h = 0; h < H_NO; h++) {
            unsigned long long a2 = 0ULL, b2 = 0ULL;
#pragma unroll
            for (int b = 0; b < COS_NO; b++) {
                unsigned long long m = mixW2[h][b];
                a2 = f32x2_fma(ua[b], m, a2);
                b2 = f32x2_fma(ub[b], m, b2);
            }
            float lo, hi;
            f32x2_unpack(a2, lo, hi);
            xa[h] = lrelu(lo + hi);
            f32x2_unpack(b2, lo, hi);
            xb[h] = lrelu(lo + hi);
        }

        unsigned long long xpa[8], xpb[8];
#pragma unroll
        for (int p = 0; p < 8; p++) {
            xpa[p] = f32x2_pack(xa[2 * p], xa[2 * p + 1]);
            xpb[p] = f32x2_pack(xb[2 * p], xb[2 * p + 1]);
        }

        float h1a[H_NO], h1b[H_NO];
#pragma unroll
        for (int o = 0; o < H_NO; o++) {
            const ulonglong2* wrow = (const ulonglong2*)&W1[o][0];
            ulonglong2 w0 = wrow[0], w1 = wrow[1], w2 = wrow[2], w3 = wrow[3];
            unsigned long long a2 = f32x2_fma(xpa[0], w0.x, 0ULL);
            unsigned long long b2 = f32x2_fma(xpb[0], w0.x, 0ULL);
            a2 = f32x2_fma(xpa[1], w0.y, a2);  b2 = f32x2_fma(xpb[1], w0.y, b2);
            a2 = f32x2_fma(xpa[2], w1.x, a2);  b2 = f32x2_fma(xpb[2], w1.x, b2);
            a2 = f32x2_fma(xpa[3], w1.y, a2);  b2 = f32x2_fma(xpb[3], w1.y, b2);
            a2 = f32x2_fma(xpa[4], w2.x, a2);  b2 = f32x2_fma(xpb[4], w2.x, b2);
            a2 = f32x2_fma(xpa[5], w2.y, a2);  b2 = f32x2_fma(xpb[5], w2.y, b2);
            a2 = f32x2_fma(xpa[6], w3.x, a2);  b2 = f32x2_fma(xpb[6], w3.x, b2);
            a2 = f32x2_fma(xpa[7], w3.y, a2);  b2 = f32x2_fma(xpb[7], w3.y, b2);
            float lo, hi;
            f32x2_unpack(a2, lo, hi);
            h1a[o] = lrelu(B1[o] + lo + hi);
            f32x2_unpack(b2, lo, hi);
            h1b[o] = lrelu(B1[o] + lo + hi);
        }

        unsigned long long hpa[8], hpb[8];
#pragma unroll
        for (int p = 0; p < 8; p++) {
            hpa[p] = f32x2_pack(h1a[2 * p], h1a[2 * p + 1]);
            hpb[p] = f32x2_pack(h1b[2 * p], h1b[2 * p + 1]);
        }

        float pacc_a = 0.0f, pacc_b = 0.0f;
#pragma unroll
        for (int o = 0; o < H_NO; o++) {
            const ulonglong2* wrow = (const ulonglong2*)&W2[o][0];
            ulonglong2 w0 = wrow[0], w1 = wrow[1], w2 = wrow[2], w3 = wrow[3];
            unsigned long long a2 = f32x2_fma(hpa[0], w0.x, 0ULL);
            unsigned long long b2 = f32x2_fma(hpb[0], w0.x, 0ULL);
            a2 = f32x2_fma(hpa[1], w0.y, a2);  b2 = f32x2_fma(hpb[1], w0.y, b2);
            a2 = f32x2_fma(hpa[2], w1.x, a2);  b2 = f32x2_fma(hpb[2], w1.x, b2);
            a2 = f32x2_fma(hpa[3], w1.y, a2);  b2 = f32x2_fma(hpb[3], w1.y, b2);
            a2 = f32x2_fma(hpa[4], w2.x, a2);  b2 = f32x2_fma(hpb[4], w2.x, b2);
            a2 = f32x2_fma(hpa[5], w2.y, a2);  b2 = f32x2_fma(hpb[5], w2.y, b2);
            a2 = f32x2_fma(hpa[6], w3.x, a2);  b2 = f32x2_fma(hpb[6], w3.x, b2);
            a2 = f32x2_fma(hpa[7], w3.y, a2);  b2 = f32x2_fma(hpb[7], w3.y, b2);
            float lo, hi;
            f32x2_unpack(a2, lo, hi);
            pacc_a = fmaf(lrelu(B2[o] + lo + hi), RW[o], pacc_a);
            f32x2_unpack(b2, lo, hi);
            pacc_b = fmaf(lrelu(B2[o] + lo + hi), RW[o], pacc_b);
        }

        int ta = t0 + tid + qq * 256;
        int tb = ta + CTHREADS;
        if (ta < T_DATA) g_partial[s][ta] = pacc_a;
        if (tb < T_DATA) g_partial[s][tb] = pacc_b;
    }
}

// ---------------------------------------------------------------------------
// Kernel 4: V[t] = sum_s partial[s][t] + root_b + V_o
// ---------------------------------------------------------------------------
__global__ void finalize(const float* __restrict__ root_b,
                         const float* __restrict__ V_o,
                         float* __restrict__ out)
{
    int t = blockIdx.x * 256 + threadIdx.x;
    if (t >= T_DATA) return;
    float sum = root_b[0] + V_o[0];
#pragma unroll
    for (int s = 0; s < SUB_NO; s++) sum += g_partial[s][t];
    out[t] = sum;
}

// ---------------------------------------------------------------------------
extern "C" void kernel_launch(void* const* d_in, const int* in_sizes, int n_in,
                              void* d_out, int out_size)
{
    const float* S_e    = (const float*)d_in[0];
    const float* S_i    = (const float*)d_in[1];
    const float* C_e    = (const float*)d_in[2];
    const float* C_i    = (const float*)d_in[3];
    const float* W_conv = (const float*)d_in[4];
    const float* ff_w   = (const float*)d_in[5];
    const float* ff_b   = (const float*)d_in[6];
    const float* ff2_w  = (const float*)d_in[7];
    const float* ff2_b  = (const float*)d_in[8];
    const float* root_w = (const float*)d_in[9];
    const float* root_b = (const float*)d_in[10];
    const float* V_o    = (const float*)d_in[11];
    (void)in_sizes; (void)n_in;

    float* out = (float*)d_out;
    const int kern_elems = SUB_NO * H_NO * 2 * T_NO;
    int write_kern = (out_size >= T_DATA + kern_elems) ? 1 : 0;

    prep_kern<<<SUB_NO, 256>>>(W_conv, out + T_DATA, write_kern);

    group_gemm<<<(T_DATA + GM_ROWS - 1) / GM_ROWS, 256>>>(S_e, S_i, C_e, C_i);

    dim3 cgrid((T_DATA + CT - 1) / CT, SUB_NO);
    conv_mlp<<<cgrid, CTHREADS>>>(W_conv, ff_w, ff_b, ff2_w, ff2_b, root_w);

    finalize<<<(T_DATA + 255) / 256, 256>>>(root_b, V_o, out);
}